// round 15
// baseline (speedup 1.0000x reference)
#include <cuda_runtime.h>
#include <cuda_fp16.h>
#include <math.h>

// Fixed shapes
#define Bq 4
#define Sq 1024
#define Dq 256
#define Hq 6
#define HDq 64
#define NHq 384          // H*Hd
#define BSq 4096         // B*S
#define BSDq (BSq*Dq)
#define NEXP 4           // slot 0 = main, 1..3 = deputies

// ---------------- scratch ----------------
__device__ __half g_hh [(size_t)NEXP*BSq*NHq];
__device__ __half g_h1h[(size_t)NEXP*BSq*NHq];
__device__ __half g_h2h[(size_t)NEXP*BSq*Dq];
__device__ float  g_es [NEXP*BSq*8];
__device__ __half g_edh[NEXP*BSq*8];             // packed fp16 ed (6 used of 8)
__device__ float  g_hsum [NEXP*Bq*NHq];
__device__ float  g_h2sum[NEXP*Bq*Dq];
__device__ float  g_gs [NEXP*BSq];
__device__ float  g_gd [NEXP*BSq];
__device__ __half g_feat_h[(size_t)BSq*Dq];
__device__ __half g_W1t_h[(size_t)NEXP*NHq*Dq];  // [e][n][k]
__device__ __half g_W2t_h[(size_t)NEXP*Dq*NHq];  // [e][n][k]
__device__ __half g_bWt_h[(size_t)Dq*Dq];        // [n][k]
__device__ float  g_main[BSDq];
__device__ float  g_depE[3*(size_t)BSDq];
__device__ float  g_bw  [BSDq];
__device__ float  g_bwsum;
__device__ unsigned char  g_rmask[3*BSq];
__device__ unsigned short g_lst[(size_t)BSq*Sq];
__device__ int g_cnt[BSq*4];

__device__ __forceinline__ float leaky02(float x){ return x > 0.f ? x : 0.2f*x; }
__device__ __forceinline__ float elu1(float x){ return x > 0.f ? x : expm1f(x); }
__device__ __forceinline__ void mma_f16(float c[4], unsigned a0,unsigned a1,unsigned a2,unsigned a3,
                                        unsigned b0,unsigned b1){
    asm volatile("mma.sync.aligned.m16n8k16.row.col.f32.f16.f16.f32 "
        "{%0,%1,%2,%3},{%4,%5,%6,%7},{%8,%9},{%0,%1,%2,%3};"
        : "+f"(c[0]),"+f"(c[1]),"+f"(c[2]),"+f"(c[3])
        : "r"(a0),"r"(a1),"r"(a2),"r"(a3),"r"(b0),"r"(b1));
}
#define LDSM4(r0,r1,r2,r3,a) \
    asm volatile("ldmatrix.sync.aligned.m8n8.x4.shared.b16 {%0,%1,%2,%3},[%4];" \
        : "=r"(r0),"=r"(r1),"=r"(r2),"=r"(r3) : "r"(a))
#define CPA16(dst,src,sz) \
    asm volatile("cp.async.cg.shared.global [%0], [%1], 16, %2;" :: "r"(dst),"l"(src),"r"(sz))
#define CPA_COMMIT() asm volatile("cp.async.commit_group;")

// ---------------- setup: prep (coalesced transposes) + router + zero + nbr ----------
__global__ void k_prep(const float* __restrict__ feature,
                       const float* __restrict__ mainW1, const float* __restrict__ depW1,
                       const float* __restrict__ mainW2, const float* __restrict__ depW2,
                       const float* __restrict__ blendW, const float* __restrict__ Wr,
                       const float* __restrict__ adj, const int* __restrict__ dnum,
                       const int* __restrict__ snum){
    __shared__ float tile[32][33];
    __shared__ int wtot[8], wpre[8], r1t[8], r2t[8];
    int task = blockIdx.y;
    int tid  = threadIdx.x;
    int i = blockIdx.x*256 + tid;
    int c = tid & 31, ty = tid >> 5;
    if (task == 0){
        g_feat_h[i] = __float2half(feature[i]);
    } else if (task == 1){
        int t = blockIdx.x;
        if (t >= NEXP*Hq*16) return;
        int e = t/(Hq*16), r1 = t%(Hq*16), h = r1/16, r2 = r1%16;
        int k0 = (r2>>1)*32, o0 = (r2&1)*32;
        const float* src = ((e==0)? mainW1 : depW1 + (size_t)(e-1)*Hq*Dq*HDq) + (size_t)h*Dq*HDq;
        #pragma unroll
        for (int rr=0;rr<4;rr++){
            int kr = ty + rr*8;
            tile[kr][c] = src[(size_t)(k0+kr)*HDq + o0 + c];
        }
        __syncthreads();
        __half* dst = g_W1t_h + (size_t)e*NHq*Dq;
        #pragma unroll
        for (int rr=0;rr<4;rr++){
            int orow = ty + rr*8;
            dst[(size_t)(h*64 + o0 + orow)*Dq + k0 + c] = __float2half(tile[c][orow]);
        }
    } else if (task == 2){
        int t = blockIdx.x;
        if (t >= NEXP*96) return;
        int e = t/96, r1 = t%96;
        int k0 = (r1>>3)*32, n0 = (r1&7)*32;
        const float* src = (e==0)? mainW2 : depW2 + (size_t)(e-1)*NHq*Dq;
        #pragma unroll
        for (int rr=0;rr<4;rr++){
            int kr = ty + rr*8;
            tile[kr][c] = src[(size_t)(k0+kr)*Dq + n0 + c];
        }
        __syncthreads();
        __half* dst = g_W2t_h + (size_t)e*Dq*NHq;
        #pragma unroll
        for (int rr=0;rr<4;rr++){
            int orow = ty + rr*8;
            dst[(size_t)(n0 + orow)*NHq + k0 + c] = __float2half(tile[c][orow]);
        }
    } else if (task == 3){
        int t = blockIdx.x;
        if (t >= 64) return;
        int k0 = (t>>3)*32, n0 = (t&7)*32;
        #pragma unroll
        for (int rr=0;rr<4;rr++){
            int kr = ty + rr*8;
            tile[kr][c] = blendW[(size_t)(k0+kr)*Dq + n0 + c];
        }
        __syncthreads();
        #pragma unroll
        for (int rr=0;rr<4;rr++){
            int orow = ty + rr*8;
            g_bWt_h[(size_t)(n0 + orow)*Dq + k0 + c] = __float2half(tile[c][orow]);
        }
    } else if (task == 4){
        int gw = blockIdx.x*8 + ty;
        if (gw >= BSq) return;
        const float* xr = feature + (size_t)gw*Dq;
        float a0=0.f,a1=0.f,a2=0.f;
        for (int k=c;k<Dq;k+=32){
            float xv = xr[k];
            a0 += xv*Wr[k*3+0]; a1 += xv*Wr[k*3+1]; a2 += xv*Wr[k*3+2];
        }
        #pragma unroll
        for (int o=16;o>0;o>>=1){
            a0 += __shfl_down_sync(0xffffffffu,a0,o);
            a1 += __shfl_down_sync(0xffffffffu,a1,o);
            a2 += __shfl_down_sync(0xffffffffu,a2,o);
        }
        if (c==0){
            float v[3]={a0,a1,a2};
            int ex=0; float mv=v[0];
            #pragma unroll
            for (int e=1;e<3;e++) if (v[e]<=mv){ mv=v[e]; ex=e; }
            #pragma unroll
            for (int e=0;e<3;e++) g_rmask[e*BSq+gw] = (e==ex)?0:1;
        }
    } else if (task == 5){
        if (i < NEXP*BSq){ g_gs[i]=0.f; g_gd[i]=0.f; }
        if (i < NEXP*Bq*NHq) g_hsum[i]=0.f;
        if (i < NEXP*Bq*Dq)  g_h2sum[i]=0.f;
        if (i==0) g_bwsum = 0.f;
    } else {
        int bs = blockIdx.x, lane = c, wid = ty;
        int doc = dnum[0], sect = snum[0];
        int lim1 = Sq - sect - doc, lim2 = Sq - doc;
        const float* arow = adj + (size_t)bs*Sq;
        float4 a = *(const float4*)(arow + tid*4);
        unsigned short loc[4]; int cc=0, ca=0, cb=0;
        float av[4] = {a.x,a.y,a.z,a.w};
        #pragma unroll
        for (int ii=0;ii<4;ii++){
            int col = tid*4+ii;
            if (av[ii] > 0.f){ loc[cc++] = (unsigned short)col; ca += (col<lim1); cb += (col<lim2); }
        }
        int scan = cc;
        #pragma unroll
        for (int off=1; off<32; off<<=1){
            int v = __shfl_up_sync(0xffffffffu, scan, off);
            if (lane>=off) scan += v;
        }
        int wca = __reduce_add_sync(0xffffffffu, (unsigned)ca);
        int wcb = __reduce_add_sync(0xffffffffu, (unsigned)cb);
        if (lane==31) wtot[wid] = scan;
        if (lane==0){ r1t[wid]=wca; r2t[wid]=wcb; }
        __syncthreads();
        if (tid==0){
            int acc=0, sa=0, sb=0;
            #pragma unroll
            for (int wdx=0; wdx<8; wdx++){
                wpre[wdx]=acc; acc+=wtot[wdx]; sa+=r1t[wdx]; sb+=r2t[wdx];
            }
            g_cnt[bs*4+0]=sa; g_cnt[bs*4+1]=sb; g_cnt[bs*4+2]=acc; g_cnt[bs*4+3]=0;
        }
        __syncthreads();
        int base = wpre[wid] + scan - cc;
        for (int ii=0;ii<cc;ii++) g_lst[(size_t)bs*Sq + base + ii] = loc[ii];
    }
}

// ---------------- fp16 GEMM: 128x64 tile, 3-stage cp.async, 1 sync/iter ----------
template<int KD, int ND, bool MASK, bool SIG, int DOT>
__global__ void __launch_bounds__(256) k_mmh(const __half* __restrict__ Abase, size_t astride,
                                             const __half* __restrict__ Btbase,
                                             float* __restrict__ Cbase, __half* __restrict__ Chbase,
                                             const float* __restrict__ bias,
                                             const float* __restrict__ asM, const float* __restrict__ asD,
                                             const float* __restrict__ adM, const float* __restrict__ adD){
    int e = blockIdx.z;
    const __half* A  = Abase + astride*e;
    const __half* Bt = Btbase + (size_t)e*ND*KD;
    float* Cf = Cbase ? Cbase + (size_t)e*BSq*ND : (float*)0;
    __half* Ch = Chbase ? Chbase + (size_t)e*BSq*ND : (__half*)0;
    int m0 = blockIdx.y*128, n0 = blockIdx.x*64;
    __shared__ __half2 As2[3][128][20];
    __shared__ __half2 Bs2[3][64][20];
    __shared__ float sred[256];
    __shared__ float sAs[64], sAd[64];
    __shared__ float sdot[256];
    __shared__ float scol[64];
    int tid=threadIdx.x, lane=tid&31, wid=tid>>5;
    int wm=(wid&3)*32, wn=(wid>>2)*32;
    int gid=lane>>2, qid=lane&3;
    bool docs = (DOT!=0) && (e>0);
    if (DOT){
        if (tid<64){
            const float* as = (e==0)? asM : asD + (size_t)(e-1)*ND;
            const float* ad = (e==0)? adM : adD + (size_t)(e-1)*ND;
            sAs[tid] = as[n0+tid];
            sAd[tid] = ad[n0+tid];
            scol[tid] = 0.f;
        }
        sdot[tid] = 0.f;
    }
    float c[2][4][4];
    #pragma unroll
    for (int mt=0;mt<2;mt++)
        #pragma unroll
        for (int nt=0;nt<4;nt++)
            #pragma unroll
            for (int r=0;r<4;r++) c[mt][nt][r]=0.f;
    int rowA = tid>>1;
    int khA  = (tid&1)*16;
    int kcA  = (tid&1)*8;
    int rowB = tid>>2;
    int khB  = (tid&3)*8;
    int kcB  = (tid&3)*4;
    bool amask = true;
    if (MASK){ if (e>0 && g_rmask[(size_t)(e-1)*BSq + m0 + rowA]==0) amask = false; }
    const __half* Ap  = A  + (size_t)(m0+rowA)*KD + khA;
    const __half* Btp = Bt + (size_t)(n0+rowB)*KD + khB;
    int szA = (MASK && !amask) ? 0 : 16;

    unsigned As_base = (unsigned)__cvta_generic_to_shared(&As2[0][0][0]);
    unsigned Bs_base = (unsigned)__cvta_generic_to_shared(&Bs2[0][0][0]);
    const unsigned STG_A = 128u*20u*4u;
    const unsigned STG_B = 64u*20u*4u;
    unsigned dstA = As_base + (unsigned)(rowA*20 + kcA)*4u;
    unsigned dstB = Bs_base + (unsigned)(rowB*20 + kcB)*4u;

#define PREFETCH(P, K0) { \
    CPA16(dstA + (unsigned)(P)*STG_A,      Ap  + (K0),     szA); \
    CPA16(dstA + (unsigned)(P)*STG_A + 16, Ap  + (K0) + 8, szA); \
    CPA16(dstB + (unsigned)(P)*STG_B,      Btp + (K0),     16); \
    CPA_COMMIT(); }

    int lr8 = lane & 7;
    int a_row = wm + lr8 + ((lane>>3)&1)*8;
    int a_kof = ((lane>>4)&1)*8;
    int b_col = wn + lr8 + ((lane>>4)&1)*8;
    int b_kof = ((lane>>3)&1)*8;
    unsigned aAddr0 = As_base + (unsigned)(a_row*40 + a_kof)*2u;
    unsigned bAddr0 = Bs_base + (unsigned)(b_col*40 + b_kof)*2u;

    const int NT = KD/32;
    PREFETCH(0, 0);
    PREFETCH(1, 32);
    int stage = 0, pstage = 2;
    for (int it=0; it<NT; it++){
        if (it+2 < NT) asm volatile("cp.async.wait_group 1;");
        else           asm volatile("cp.async.wait_group 0;");
        __syncthreads();
        if (it+2 < NT){
            PREFETCH(pstage, (it+2)*32);
            pstage = (pstage+1 == 3) ? 0 : pstage+1;
        }
        unsigned stA = (unsigned)stage*STG_A;
        unsigned stB = (unsigned)stage*STG_B;
        stage = (stage+1 == 3) ? 0 : stage+1;
        #pragma unroll
        for (int sub=0; sub<2; sub++){
            unsigned af[2][4], bf[2][4];
            #pragma unroll
            for (int mt=0;mt<2;mt++){
                unsigned ad = aAddr0 + stA + (unsigned)(mt*16*40 + sub*16)*2u;
                LDSM4(af[mt][0],af[mt][1],af[mt][2],af[mt][3], ad);
            }
            #pragma unroll
            for (int ntp=0;ntp<2;ntp++){
                unsigned bd = bAddr0 + stB + (unsigned)(ntp*16*40 + sub*16)*2u;
                LDSM4(bf[ntp][0],bf[ntp][1],bf[ntp][2],bf[ntp][3], bd);
            }
            #pragma unroll
            for (int mt=0;mt<2;mt++)
                #pragma unroll
                for (int nt=0;nt<4;nt++)
                    mma_f16(c[mt][nt], af[mt][0],af[mt][1],af[mt][2],af[mt][3],
                            bf[nt>>1][(nt&1)*2], bf[nt>>1][(nt&1)*2+1]);
        }
    }
#undef PREFETCH
    float lsum = 0.f;
    float colp[8];
    #pragma unroll
    for (int i=0;i<8;i++) colp[i]=0.f;
    #pragma unroll
    for (int mt=0;mt<2;mt++){
        int orow = m0 + wm + mt*16 + gid;
        float ds0=0.f, dd0=0.f, ds1=0.f, dd1=0.f;
        #pragma unroll
        for (int nt=0;nt<4;nt++){
            int lcol = wn + nt*8 + qid*2;
            int col = n0 + lcol;
            float2 v0 = make_float2(c[mt][nt][0], c[mt][nt][1]);
            float2 v1 = make_float2(c[mt][nt][2], c[mt][nt][3]);
            if (SIG){
                float b0v = bias[col], b1v = bias[col+1];
                v0.x = 1.f/(1.f+__expf(-(v0.x+b0v))); v0.y = 1.f/(1.f+__expf(-(v0.y+b1v)));
                v1.x = 1.f/(1.f+__expf(-(v1.x+b0v))); v1.y = 1.f/(1.f+__expf(-(v1.y+b1v)));
                lsum += v0.x+v0.y+v1.x+v1.y;
            }
            if (DOT){
                float a0=sAs[lcol], a1=sAs[lcol+1], d0=sAd[lcol], d1=sAd[lcol+1];
                ds0 += v0.x*a0 + v0.y*a1;  dd0 += v0.x*d0 + v0.y*d1;
                ds1 += v1.x*a0 + v1.y*a1;  dd1 += v1.x*d0 + v1.y*d1;
                if (docs){
                    colp[nt*2]   += v0.x + v1.x;
                    colp[nt*2+1] += v0.y + v1.y;
                }
            }
            if (Cf){
                *(float2*)&Cf[(size_t)orow*ND + col]     = v0;
                *(float2*)&Cf[(size_t)(orow+8)*ND + col] = v1;
            }
            if (Ch){
                *(__half2*)&Ch[(size_t)orow*ND + col]     = __float22half2_rn(v0);
                *(__half2*)&Ch[(size_t)(orow+8)*ND + col] = __float22half2_rn(v1);
            }
        }
        if (DOT){
            ds0 += __shfl_down_sync(0xffffffffu, ds0, 2, 4); ds0 += __shfl_down_sync(0xffffffffu, ds0, 1, 4);
            dd0 += __shfl_down_sync(0xffffffffu, dd0, 2, 4); dd0 += __shfl_down_sync(0xffffffffu, dd0, 1, 4);
            ds1 += __shfl_down_sync(0xffffffffu, ds1, 2, 4); ds1 += __shfl_down_sync(0xffffffffu, ds1, 1, 4);
            dd1 += __shfl_down_sync(0xffffffffu, dd1, 2, 4); dd1 += __shfl_down_sync(0xffffffffu, dd1, 1, 4);
            if (qid==0){
                int rl = wm + mt*16 + gid;
                atomicAdd(&sdot[rl],     ds0); atomicAdd(&sdot[rl+8],     ds1);
                atomicAdd(&sdot[128+rl], dd0); atomicAdd(&sdot[128+rl+8], dd1);
            }
        }
    }
    if (docs){
        #pragma unroll
        for (int i=0;i<8;i++){
            colp[i] += __shfl_down_sync(0xffffffffu, colp[i], 16);
            colp[i] += __shfl_down_sync(0xffffffffu, colp[i], 8);
            colp[i] += __shfl_down_sync(0xffffffffu, colp[i], 4);
        }
        if (lane < 4){
            #pragma unroll
            for (int nt=0;nt<4;nt++){
                atomicAdd(&scol[wn + nt*8 + qid*2],     colp[nt*2]);
                atomicAdd(&scol[wn + nt*8 + qid*2 + 1], colp[nt*2+1]);
            }
        }
    }
    if (DOT){
        __syncthreads();
        if (tid<128){
            if (DOT==1){
                size_t idx = ((size_t)e*BSq + m0 + tid)*8 + (n0>>6);
                g_es[idx]  = sdot[tid];
                g_edh[idx] = __float2half(sdot[128+tid]);
            } else {
                atomicAdd(&g_gs[(size_t)e*BSq + m0 + tid], sdot[tid]);
                atomicAdd(&g_gd[(size_t)e*BSq + m0 + tid], sdot[128+tid]);
            }
        }
        if (docs && tid<64){
            int eb = e*Bq + (m0>>10);
            if (DOT==1) atomicAdd(&g_hsum [(size_t)eb*NHq + n0 + tid], scol[tid]);
            else        atomicAdd(&g_h2sum[(size_t)eb*Dq  + n0 + tid], scol[tid]);
        }
    }
    if (SIG){
        sred[tid] = lsum;
        __syncthreads();
        for (int st=128; st>0; st>>=1){ if (tid<st) sred[tid]+=sred[tid+st]; __syncthreads(); }
        if (tid==0) atomicAdd(&g_bwsum, sred[0]);
    }
}

// ---------------- attention layer 1 (single-pass softmax, no max, __expf) ----------
__global__ void __launch_bounds__(192) k_att1(){
    __shared__ unsigned short lst[1024];
    __shared__ unsigned char  ok[1024];
    __shared__ float wf[6*1024];
    __shared__ float sred[6][8];
    __shared__ float ssum[6];
    __shared__ float es6[6];
    __shared__ float4 sacc[2][96];
    int bs = blockIdx.x, ex = blockIdx.y, b = bs>>10;
    int tid = threadIdx.x, lane = tid&31, wid = tid>>5;
    int c1 = g_cnt[bs*4+0], c2 = g_cnt[bs*4+1], ct = g_cnt[bs*4+2];
    int lo, hi;
    if      (ex==0){ lo=0;  hi=ct; }
    else if (ex==1){ lo=0;  hi=c1; }
    else if (ex==2){ lo=c1; hi=c2; }
    else           { lo=c2; hi=ct; }
    int n = hi-lo;
    __half* h1row = g_h1h + ((size_t)ex*BSq + bs)*NHq;
    if (n==0){
        if (tid<96){
            float4 hv = *(const float4*)&g_hsum[(size_t)((ex<<2)|b)*NHq + tid*4];
            *(__half2*)&h1row[tid*4]   = __float22half2_rn(make_float2(elu1(hv.x*(1.f/Sq)), elu1(hv.y*(1.f/Sq))));
            *(__half2*)&h1row[tid*4+2] = __float22half2_rn(make_float2(elu1(hv.z*(1.f/Sq)), elu1(hv.w*(1.f/Sq))));
        }
        return;
    }
    for (int j=tid;j<n;j+=192) lst[j] = g_lst[(size_t)bs*Sq + lo + j];
    if (tid<6) es6[tid] = g_es[((size_t)ex*BSq + bs)*8 + tid];
    __syncthreads();
    const __half* edb = g_edh + ((size_t)ex*BSq + ((size_t)b<<10))*8;
    const unsigned char* rm = (ex>0)? g_rmask + (size_t)(ex-1)*BSq + (b<<10) : nullptr;
    // single pass: exp-logit + sum (no max subtraction; logits are O(10), fp32-safe)
    float sm[6] = {0.f,0.f,0.f,0.f,0.f,0.f};
    for (int j=tid;j<n;j+=192){
        int nb = lst[j];
        uint4 raw = *(const uint4*)&edb[nb*8];
        ok[j] = rm ? rm[nb] : 1;
        float2 q0 = __half22float2(*(__half2*)&raw.x);
        float2 q1 = __half22float2(*(__half2*)&raw.y);
        float2 q2 = __half22float2(*(__half2*)&raw.z);
        float ev[6] = {q0.x,q0.y,q1.x,q1.y,q2.x,q2.y};
        #pragma unroll
        for (int h=0;h<6;h++){
            float ww = __expf(leaky02(es6[h] + ev[h]));
            wf[h*1024+j] = ww;
            sm[h] += ww;
        }
    }
    #pragma unroll
    for (int h=0;h<6;h++){
        #pragma unroll
        for (int o=16;o>0;o>>=1) sm[h] += __shfl_xor_sync(0xffffffffu, sm[h], o);
    }
    if (lane==0){
        #pragma unroll
        for (int h=0;h<6;h++) sred[h][wid] = sm[h];
    }
    __syncthreads();
    if (tid<6){
        float s = sred[tid][0];
        #pragma unroll
        for (int wdx=1; wdx<6; wdx++) s += sred[tid][wdx];
        ssum[tid] = s;
    }
    __syncthreads();
    {
        int col = tid % 96, grp = tid / 96;
        int h = col >> 4;
        const __half* hb = g_hh + ((size_t)ex*BSq + ((size_t)b<<10))*NHq;
        float ax=0.f, ay=0.f, az=0.f, aw=0.f;
        if (ex==0){
            int j = grp;
            for (; j+2 < n; j += 4){
                float w0 = wf[h*1024+j];
                float w1 = wf[h*1024+j+2];
                uint2 r0 = *(const uint2*)&hb[(size_t)lst[j]*NHq   + col*4];
                uint2 r1 = *(const uint2*)&hb[(size_t)lst[j+2]*NHq + col*4];
                float2 p00 = __half22float2(*(__half2*)&r0.x);
                float2 p01 = __half22float2(*(__half2*)&r0.y);
                float2 p10 = __half22float2(*(__half2*)&r1.x);
                float2 p11 = __half22float2(*(__half2*)&r1.y);
                ax += w0*p00.x + w1*p10.x; ay += w0*p00.y + w1*p10.y;
                az += w0*p01.x + w1*p11.x; aw += w0*p01.y + w1*p11.y;
            }
            for (; j < n; j += 2){
                float w0 = wf[h*1024+j];
                uint2 r0 = *(const uint2*)&hb[(size_t)lst[j]*NHq + col*4];
                float2 p00 = __half22float2(*(__half2*)&r0.x);
                float2 p01 = __half22float2(*(__half2*)&r0.y);
                ax += w0*p00.x; ay += w0*p00.y; az += w0*p01.x; aw += w0*p01.y;
            }
        } else {
            for (int j=grp; j<n; j+=2){
                if (!ok[j]) continue;
                float w0 = wf[h*1024+j];
                uint2 r0 = *(const uint2*)&hb[(size_t)lst[j]*NHq + col*4];
                float2 p00 = __half22float2(*(__half2*)&r0.x);
                float2 p01 = __half22float2(*(__half2*)&r0.y);
                ax += w0*p00.x; ay += w0*p00.y; az += w0*p01.x; aw += w0*p01.y;
            }
        }
        sacc[grp][col] = make_float4(ax,ay,az,aw);
    }
    __syncthreads();
    if (tid<96){
        int h = tid >> 4;
        float inv = 1.f/ssum[h];
        float4 a0 = sacc[0][tid], a1 = sacc[1][tid];
        *(__half2*)&h1row[tid*4]   = __float22half2_rn(make_float2(elu1((a0.x+a1.x)*inv), elu1((a0.y+a1.y)*inv)));
        *(__half2*)&h1row[tid*4+2] = __float22half2_rn(make_float2(elu1((a0.z+a1.z)*inv), elu1((a0.w+a1.w)*inv)));
    }
}

// ---------------- attention layer 2 (single-pass softmax, __expf) ----------------
__global__ void __launch_bounds__(256) k_att2(){
    __shared__ unsigned short lst[1024];
    __shared__ float w[1024];
    __shared__ float red[256];
    __shared__ float4 sacc[4][64];
    int bs = blockIdx.x, ex = blockIdx.y, b = bs>>10;
    int tid = threadIdx.x;
    if (ex>0 && g_rmask[(size_t)(ex-1)*BSq + bs]==0) return;
    float* outb = (ex==0)? g_main : g_depE + (size_t)(ex-1)*BSDq;
    int c1 = g_cnt[bs*4+0], c2 = g_cnt[bs*4+1], ct = g_cnt[bs*4+2];
    int lo, hi;
    if      (ex==0){ lo=0;  hi=ct; }
    else if (ex==1){ lo=0;  hi=c1; }
    else if (ex==2){ lo=c1; hi=c2; }
    else           { lo=c2; hi=ct; }
    int n = hi-lo;
    if (n==0){
        if (tid<64){
            float4 hv = *(const float4*)&g_h2sum[(size_t)((ex<<2)|b)*Dq + tid*4];
            *(float4*)&outb[(size_t)bs*Dq + tid*4] =
                make_float4(hv.x*(1.f/Sq), hv.y*(1.f/Sq), hv.z*(1.f/Sq), hv.w*(1.f/Sq));
        }
        return;
    }
    for (int j=tid;j<n;j+=256) lst[j] = g_lst[(size_t)bs*Sq + lo + j];
    __syncthreads();
    float gsv = g_gs[(size_t)ex*BSq + bs];
    const float* gdb = g_gd + (size_t)ex*BSq + (b<<10);
    float sloc = 0.f;
    for (int j=tid;j<n;j+=256){
        float ww = __expf(leaky02(gsv + gdb[lst[j]]));
        w[j] = ww;
        sloc += ww;
    }
    red[tid]=sloc; __syncthreads();
    for (int st=128;st>0;st>>=1){ if (tid<st) red[tid]+=red[tid+st]; __syncthreads(); }
    float inv = 1.f/red[0];
    int grp = tid>>6, q = tid&63;
    const __half* h2b = g_h2h + ((size_t)ex*BSq + ((size_t)b<<10))*Dq;
    float ax=0.f, ay=0.f, az=0.f, aw=0.f;
    int j = grp;
    for (; j+4 < n; j += 8){
        float w0 = w[j], w1 = w[j+4];
        uint2 r0 = *(const uint2*)&h2b[(size_t)lst[j]*Dq   + q*4];
        uint2 r1 = *(const uint2*)&h2b[(size_t)lst[j+4]*Dq + q*4];
        float2 p00 = __half22float2(*(__half2*)&r0.x);
        float2 p01 = __half22float2(*(__half2*)&r0.y);
        float2 p10 = __half22float2(*(__half2*)&r1.x);
        float2 p11 = __half22float2(*(__half2*)&r1.y);
        ax += w0*p00.x + w1*p10.x; ay += w0*p00.y + w1*p10.y;
        az += w0*p01.x + w1*p11.x; aw += w0*p01.y + w1*p11.y;
    }
    for (; j < n; j += 4){
        float w0 = w[j];
        uint2 r0 = *(const uint2*)&h2b[(size_t)lst[j]*Dq + q*4];
        float2 p00 = __half22float2(*(__half2*)&r0.x);
        float2 p01 = __half22float2(*(__half2*)&r0.y);
        ax += w0*p00.x; ay += w0*p00.y; az += w0*p01.x; aw += w0*p01.y;
    }
    sacc[grp][q] = make_float4(ax,ay,az,aw);
    __syncthreads();
    if (tid<64){
        float4 a0=sacc[0][tid], a1=sacc[1][tid], a2=sacc[2][tid], a3=sacc[3][tid];
        *(float4*)&outb[(size_t)bs*Dq + tid*4] =
            make_float4((a0.x+a1.x+a2.x+a3.x)*inv, (a0.y+a1.y+a2.y+a3.y)*inv,
                        (a0.z+a1.z+a2.z+a3.z)*inv, (a0.w+a1.w+a2.w+a3.w)*inv);
    }
}

// ---------------- final blend ----------------
__global__ void k_final(float* __restrict__ out){
    __shared__ unsigned char msk[3];
    int bs = blockIdx.x, d = threadIdx.x;
    if (d<3) msk[d] = g_rmask[d*BSq+bs];
    __syncthreads();
    size_t i = (size_t)bs*Dq + d;
    float dep = 0.f;
    if (msk[0]) dep += g_depE[i];
    if (msk[1]) dep += g_depE[BSDq + i];
    if (msk[2]) dep += g_depE[2*(size_t)BSDq + i];
    float bw = g_bw[i];
    out[i] = bw*g_main[i] + (1.f-bw)*dep;
    if (bs==0 && d==0){
        float mc = g_bwsum * (1.f/(float)BSDq);
        out[BSDq]   = fabsf(mc - 0.6f) * 0.01f;
        out[BSDq+1] = mc;
    }
}

// ---------------- host launcher ----------------
extern "C" void kernel_launch(void* const* d_in, const int* in_sizes, int n_in,
                              void* d_out, int out_size){
    const float* feature  = (const float*)d_in[0];
    const float* adj      = (const float*)d_in[1];
    const float* main_W1  = (const float*)d_in[2];
    const float* main_a1s = (const float*)d_in[3];
    const float* main_a1d = (const float*)d_in[4];
    const float* main_W2  = (const float*)d_in[5];
    const float* main_a2s = (const float*)d_in[6];
    const float* main_a2d = (const float*)d_in[7];
    const float* dep_W1   = (const float*)d_in[8];
    const float* dep_a1s  = (const float*)d_in[9];
    const float* dep_a1d  = (const float*)d_in[10];
    const float* dep_W2   = (const float*)d_in[11];
    const float* dep_a2s  = (const float*)d_in[12];
    const float* dep_a2d  = (const float*)d_in[13];
    const float* router_W = (const float*)d_in[14];
    const float* blend_W  = (const float*)d_in[15];
    const float* blend_b  = (const float*)d_in[16];
    const int*   doc_num  = (const int*)d_in[17];
    const int*   sect_num = (const int*)d_in[18];
    float* out = (float*)d_out;

    __half* feat_h;  cudaGetSymbolAddress((void**)&feat_h,  g_feat_h);
    __half* W1t_h;   cudaGetSymbolAddress((void**)&W1t_h,   g_W1t_h);
    __half* W2t_h;   cudaGetSymbolAddress((void**)&W2t_h,   g_W2t_h);
    __half* bWt_h;   cudaGetSymbolAddress((void**)&bWt_h,   g_bWt_h);
    __half* h1h_p;   cudaGetSymbolAddress((void**)&h1h_p,   g_h1h);
    float*  bw_p;    cudaGetSymbolAddress((void**)&bw_p,    g_bw);
    __half* hh_p;    cudaGetSymbolAddress((void**)&hh_p,    g_hh);
    __half* h2h_p;   cudaGetSymbolAddress((void**)&h2h_p,   g_h2h);

    k_prep<<<dim3(BSq*Dq/256, 7), 256>>>(feature, main_W1, dep_W1, main_W2, dep_W2,
                                         blend_W, router_W, adj, doc_num, sect_num);

    k_mmh<Dq, Dq, false, true, 0><<<dim3(4,32,1), 256>>>(feat_h, 0, bWt_h, bw_p, (__half*)0, blend_b,
                                                         (const float*)0,(const float*)0,(const float*)0,(const float*)0);

    k_mmh<Dq, NHq, true, false, 1><<<dim3(6,32,NEXP), 256>>>(feat_h, 0, W1t_h, (float*)0, hh_p, (const float*)0,
                                                             main_a1s, dep_a1s, main_a1d, dep_a1d);
    k_att1<<<dim3(BSq, NEXP), 192>>>();

    k_mmh<NHq, Dq, false, false, 2><<<dim3(4,32,NEXP), 256>>>(h1h_p, (size_t)BSq*NHq, W2t_h, (float*)0, h2h_p, (const float*)0,
                                                              main_a2s, dep_a2s, main_a2d, dep_a2d);
    k_att2<<<dim3(BSq, NEXP), 256>>>();

    k_final<<<BSq, Dq>>>(out);
}

// round 16
// speedup vs baseline: 1.0464x; 1.0464x over previous
#include <cuda_runtime.h>
#include <cuda_fp16.h>
#include <math.h>

// Fixed shapes
#define Bq 4
#define Sq 1024
#define Dq 256
#define Hq 6
#define HDq 64
#define NHq 384          // H*Hd
#define BSq 4096         // B*S
#define BSDq (BSq*Dq)
#define NEXP 4           // slot 0 = main, 1..3 = deputies

// ---------------- scratch ----------------
__device__ __half g_hh [(size_t)NEXP*BSq*NHq];
__device__ __half g_h1h[(size_t)NEXP*BSq*NHq];
__device__ __half g_h2h[(size_t)NEXP*BSq*Dq];
__device__ float  g_es [NEXP*BSq*8];
__device__ __half g_edh[NEXP*BSq*8];             // packed fp16 ed (6 used of 8)
__device__ float  g_hsum [NEXP*Bq*NHq];
__device__ float  g_h2sum[NEXP*Bq*Dq];
__device__ float  g_gs [NEXP*BSq];
__device__ float  g_gd [NEXP*BSq];
__device__ __half g_feat_h[(size_t)BSq*Dq];
__device__ __half g_W1t_h[(size_t)NEXP*NHq*Dq];  // [e][n][k]
__device__ __half g_W2t_h[(size_t)NEXP*Dq*NHq];  // [e][n][k]
__device__ __half g_bWt_h[(size_t)Dq*Dq];        // [n][k]
__device__ float  g_main[BSDq];
__device__ float  g_depE[3*(size_t)BSDq];
__device__ float  g_bw  [BSDq];
__device__ float  g_bwsum;
__device__ unsigned char  g_rmask[3*BSq];
__device__ unsigned short g_lst[(size_t)BSq*Sq];
__device__ int g_cnt[BSq*4];

__device__ __forceinline__ float leaky02(float x){ return x > 0.f ? x : 0.2f*x; }
__device__ __forceinline__ float elu1(float x){ return x > 0.f ? x : expm1f(x); }
__device__ __forceinline__ void mma_f16(float c[4], unsigned a0,unsigned a1,unsigned a2,unsigned a3,
                                        unsigned b0,unsigned b1){
    asm volatile("mma.sync.aligned.m16n8k16.row.col.f32.f16.f16.f32 "
        "{%0,%1,%2,%3},{%4,%5,%6,%7},{%8,%9},{%0,%1,%2,%3};"
        : "+f"(c[0]),"+f"(c[1]),"+f"(c[2]),"+f"(c[3])
        : "r"(a0),"r"(a1),"r"(a2),"r"(a3),"r"(b0),"r"(b1));
}
#define LDSM4(r0,r1,r2,r3,a) \
    asm volatile("ldmatrix.sync.aligned.m8n8.x4.shared.b16 {%0,%1,%2,%3},[%4];" \
        : "=r"(r0),"=r"(r1),"=r"(r2),"=r"(r3) : "r"(a))
#define CPA16(dst,src,sz) \
    asm volatile("cp.async.cg.shared.global [%0], [%1], 16, %2;" :: "r"(dst),"l"(src),"r"(sz))
#define CPA_COMMIT() asm volatile("cp.async.commit_group;")

// ---------------- setup: prep (coalesced transposes) + router + zero + nbr ----------
__global__ void k_prep(const float* __restrict__ feature,
                       const float* __restrict__ mainW1, const float* __restrict__ depW1,
                       const float* __restrict__ mainW2, const float* __restrict__ depW2,
                       const float* __restrict__ blendW, const float* __restrict__ Wr,
                       const float* __restrict__ adj, const int* __restrict__ dnum,
                       const int* __restrict__ snum){
    __shared__ float tile[32][33];
    __shared__ int wtot[8], wpre[8], r1t[8], r2t[8];
    int task = blockIdx.y;
    int tid  = threadIdx.x;
    int i = blockIdx.x*256 + tid;
    int c = tid & 31, ty = tid >> 5;
    if (task == 0){
        g_feat_h[i] = __float2half(feature[i]);
    } else if (task == 1){
        int t = blockIdx.x;
        if (t >= NEXP*Hq*16) return;
        int e = t/(Hq*16), r1 = t%(Hq*16), h = r1/16, r2 = r1%16;
        int k0 = (r2>>1)*32, o0 = (r2&1)*32;
        const float* src = ((e==0)? mainW1 : depW1 + (size_t)(e-1)*Hq*Dq*HDq) + (size_t)h*Dq*HDq;
        #pragma unroll
        for (int rr=0;rr<4;rr++){
            int kr = ty + rr*8;
            tile[kr][c] = src[(size_t)(k0+kr)*HDq + o0 + c];
        }
        __syncthreads();
        __half* dst = g_W1t_h + (size_t)e*NHq*Dq;
        #pragma unroll
        for (int rr=0;rr<4;rr++){
            int orow = ty + rr*8;
            dst[(size_t)(h*64 + o0 + orow)*Dq + k0 + c] = __float2half(tile[c][orow]);
        }
    } else if (task == 2){
        int t = blockIdx.x;
        if (t >= NEXP*96) return;
        int e = t/96, r1 = t%96;
        int k0 = (r1>>3)*32, n0 = (r1&7)*32;
        const float* src = (e==0)? mainW2 : depW2 + (size_t)(e-1)*NHq*Dq;
        #pragma unroll
        for (int rr=0;rr<4;rr++){
            int kr = ty + rr*8;
            tile[kr][c] = src[(size_t)(k0+kr)*Dq + n0 + c];
        }
        __syncthreads();
        __half* dst = g_W2t_h + (size_t)e*Dq*NHq;
        #pragma unroll
        for (int rr=0;rr<4;rr++){
            int orow = ty + rr*8;
            dst[(size_t)(n0 + orow)*NHq + k0 + c] = __float2half(tile[c][orow]);
        }
    } else if (task == 3){
        int t = blockIdx.x;
        if (t >= 64) return;
        int k0 = (t>>3)*32, n0 = (t&7)*32;
        #pragma unroll
        for (int rr=0;rr<4;rr++){
            int kr = ty + rr*8;
            tile[kr][c] = blendW[(size_t)(k0+kr)*Dq + n0 + c];
        }
        __syncthreads();
        #pragma unroll
        for (int rr=0;rr<4;rr++){
            int orow = ty + rr*8;
            g_bWt_h[(size_t)(n0 + orow)*Dq + k0 + c] = __float2half(tile[c][orow]);
        }
    } else if (task == 4){
        int gw = blockIdx.x*8 + ty;
        if (gw >= BSq) return;
        const float* xr = feature + (size_t)gw*Dq;
        float a0=0.f,a1=0.f,a2=0.f;
        for (int k=c;k<Dq;k+=32){
            float xv = xr[k];
            a0 += xv*Wr[k*3+0]; a1 += xv*Wr[k*3+1]; a2 += xv*Wr[k*3+2];
        }
        #pragma unroll
        for (int o=16;o>0;o>>=1){
            a0 += __shfl_down_sync(0xffffffffu,a0,o);
            a1 += __shfl_down_sync(0xffffffffu,a1,o);
            a2 += __shfl_down_sync(0xffffffffu,a2,o);
        }
        if (c==0){
            float v[3]={a0,a1,a2};
            int ex=0; float mv=v[0];
            #pragma unroll
            for (int e=1;e<3;e++) if (v[e]<=mv){ mv=v[e]; ex=e; }
            #pragma unroll
            for (int e=0;e<3;e++) g_rmask[e*BSq+gw] = (e==ex)?0:1;
        }
    } else if (task == 5){
        if (i < NEXP*BSq){ g_gs[i]=0.f; g_gd[i]=0.f; }
        if (i < NEXP*Bq*NHq) g_hsum[i]=0.f;
        if (i < NEXP*Bq*Dq)  g_h2sum[i]=0.f;
        if (i==0) g_bwsum = 0.f;
    } else {
        int bs = blockIdx.x, lane = c, wid = ty;
        int doc = dnum[0], sect = snum[0];
        int lim1 = Sq - sect - doc, lim2 = Sq - doc;
        const float* arow = adj + (size_t)bs*Sq;
        float4 a = *(const float4*)(arow + tid*4);
        unsigned short loc[4]; int cc=0, ca=0, cb=0;
        float av[4] = {a.x,a.y,a.z,a.w};
        #pragma unroll
        for (int ii=0;ii<4;ii++){
            int col = tid*4+ii;
            if (av[ii] > 0.f){ loc[cc++] = (unsigned short)col; ca += (col<lim1); cb += (col<lim2); }
        }
        int scan = cc;
        #pragma unroll
        for (int off=1; off<32; off<<=1){
            int v = __shfl_up_sync(0xffffffffu, scan, off);
            if (lane>=off) scan += v;
        }
        int wca = __reduce_add_sync(0xffffffffu, (unsigned)ca);
        int wcb = __reduce_add_sync(0xffffffffu, (unsigned)cb);
        if (lane==31) wtot[wid] = scan;
        if (lane==0){ r1t[wid]=wca; r2t[wid]=wcb; }
        __syncthreads();
        if (tid==0){
            int acc=0, sa=0, sb=0;
            #pragma unroll
            for (int wdx=0; wdx<8; wdx++){
                wpre[wdx]=acc; acc+=wtot[wdx]; sa+=r1t[wdx]; sb+=r2t[wdx];
            }
            g_cnt[bs*4+0]=sa; g_cnt[bs*4+1]=sb; g_cnt[bs*4+2]=acc; g_cnt[bs*4+3]=0;
        }
        __syncthreads();
        int base = wpre[wid] + scan - cc;
        for (int ii=0;ii<cc;ii++) g_lst[(size_t)bs*Sq + base + ii] = loc[ii];
    }
}

// ---------------- fp16 GEMM: 128x64 tile, 3-stage cp.async, 1 sync/iter ----------
template<int KD, int ND, bool MASK, bool SIG, int DOT>
__global__ void __launch_bounds__(256) k_mmh(const __half* __restrict__ Abase, size_t astride,
                                             const __half* __restrict__ Btbase,
                                             float* __restrict__ Cbase, __half* __restrict__ Chbase,
                                             const float* __restrict__ bias,
                                             const float* __restrict__ asM, const float* __restrict__ asD,
                                             const float* __restrict__ adM, const float* __restrict__ adD){
    int e = blockIdx.z;
    const __half* A  = Abase + astride*e;
    const __half* Bt = Btbase + (size_t)e*ND*KD;
    float* Cf = Cbase ? Cbase + (size_t)e*BSq*ND : (float*)0;
    __half* Ch = Chbase ? Chbase + (size_t)e*BSq*ND : (__half*)0;
    int m0 = blockIdx.y*128, n0 = blockIdx.x*64;
    __shared__ __half2 As2[3][128][20];
    __shared__ __half2 Bs2[3][64][20];
    __shared__ float sred[256];
    __shared__ float sAs[64], sAd[64];
    __shared__ float sdot[256];
    __shared__ float scol[64];
    int tid=threadIdx.x, lane=tid&31, wid=tid>>5;
    int wm=(wid&3)*32, wn=(wid>>2)*32;
    int gid=lane>>2, qid=lane&3;
    bool docs = (DOT!=0) && (e>0);
    if (DOT){
        if (tid<64){
            const float* as = (e==0)? asM : asD + (size_t)(e-1)*ND;
            const float* ad = (e==0)? adM : adD + (size_t)(e-1)*ND;
            sAs[tid] = as[n0+tid];
            sAd[tid] = ad[n0+tid];
            scol[tid] = 0.f;
        }
        sdot[tid] = 0.f;
    }
    float c[2][4][4];
    #pragma unroll
    for (int mt=0;mt<2;mt++)
        #pragma unroll
        for (int nt=0;nt<4;nt++)
            #pragma unroll
            for (int r=0;r<4;r++) c[mt][nt][r]=0.f;
    int rowA = tid>>1;
    int khA  = (tid&1)*16;
    int kcA  = (tid&1)*8;
    int rowB = tid>>2;
    int khB  = (tid&3)*8;
    int kcB  = (tid&3)*4;
    bool amask = true;
    if (MASK){ if (e>0 && g_rmask[(size_t)(e-1)*BSq + m0 + rowA]==0) amask = false; }
    const __half* Ap  = A  + (size_t)(m0+rowA)*KD + khA;
    const __half* Btp = Bt + (size_t)(n0+rowB)*KD + khB;
    int szA = (MASK && !amask) ? 0 : 16;

    unsigned As_base = (unsigned)__cvta_generic_to_shared(&As2[0][0][0]);
    unsigned Bs_base = (unsigned)__cvta_generic_to_shared(&Bs2[0][0][0]);
    const unsigned STG_A = 128u*20u*4u;
    const unsigned STG_B = 64u*20u*4u;
    unsigned dstA = As_base + (unsigned)(rowA*20 + kcA)*4u;
    unsigned dstB = Bs_base + (unsigned)(rowB*20 + kcB)*4u;

#define PREFETCH(P, K0) { \
    CPA16(dstA + (unsigned)(P)*STG_A,      Ap  + (K0),     szA); \
    CPA16(dstA + (unsigned)(P)*STG_A + 16, Ap  + (K0) + 8, szA); \
    CPA16(dstB + (unsigned)(P)*STG_B,      Btp + (K0),     16); \
    CPA_COMMIT(); }

    int lr8 = lane & 7;
    int a_row = wm + lr8 + ((lane>>3)&1)*8;
    int a_kof = ((lane>>4)&1)*8;
    int b_col = wn + lr8 + ((lane>>4)&1)*8;
    int b_kof = ((lane>>3)&1)*8;
    unsigned aAddr0 = As_base + (unsigned)(a_row*40 + a_kof)*2u;
    unsigned bAddr0 = Bs_base + (unsigned)(b_col*40 + b_kof)*2u;

    const int NT = KD/32;
    PREFETCH(0, 0);
    PREFETCH(1, 32);
    int stage = 0, pstage = 2;
    for (int it=0; it<NT; it++){
        if (it+2 < NT) asm volatile("cp.async.wait_group 1;");
        else           asm volatile("cp.async.wait_group 0;");
        __syncthreads();
        if (it+2 < NT){
            PREFETCH(pstage, (it+2)*32);
            pstage = (pstage+1 == 3) ? 0 : pstage+1;
        }
        unsigned stA = (unsigned)stage*STG_A;
        unsigned stB = (unsigned)stage*STG_B;
        stage = (stage+1 == 3) ? 0 : stage+1;
        #pragma unroll
        for (int sub=0; sub<2; sub++){
            unsigned af[2][4], bf[2][4];
            #pragma unroll
            for (int mt=0;mt<2;mt++){
                unsigned ad = aAddr0 + stA + (unsigned)(mt*16*40 + sub*16)*2u;
                LDSM4(af[mt][0],af[mt][1],af[mt][2],af[mt][3], ad);
            }
            #pragma unroll
            for (int ntp=0;ntp<2;ntp++){
                unsigned bd = bAddr0 + stB + (unsigned)(ntp*16*40 + sub*16)*2u;
                LDSM4(bf[ntp][0],bf[ntp][1],bf[ntp][2],bf[ntp][3], bd);
            }
            #pragma unroll
            for (int mt=0;mt<2;mt++)
                #pragma unroll
                for (int nt=0;nt<4;nt++)
                    mma_f16(c[mt][nt], af[mt][0],af[mt][1],af[mt][2],af[mt][3],
                            bf[nt>>1][(nt&1)*2], bf[nt>>1][(nt&1)*2+1]);
        }
    }
#undef PREFETCH
    float lsum = 0.f;
    float colp[8];
    #pragma unroll
    for (int i=0;i<8;i++) colp[i]=0.f;
    #pragma unroll
    for (int mt=0;mt<2;mt++){
        int orow = m0 + wm + mt*16 + gid;
        float ds0=0.f, dd0=0.f, ds1=0.f, dd1=0.f;
        #pragma unroll
        for (int nt=0;nt<4;nt++){
            int lcol = wn + nt*8 + qid*2;
            int col = n0 + lcol;
            float2 v0 = make_float2(c[mt][nt][0], c[mt][nt][1]);
            float2 v1 = make_float2(c[mt][nt][2], c[mt][nt][3]);
            if (SIG){
                float b0v = bias[col], b1v = bias[col+1];
                v0.x = 1.f/(1.f+__expf(-(v0.x+b0v))); v0.y = 1.f/(1.f+__expf(-(v0.y+b1v)));
                v1.x = 1.f/(1.f+__expf(-(v1.x+b0v))); v1.y = 1.f/(1.f+__expf(-(v1.y+b1v)));
                lsum += v0.x+v0.y+v1.x+v1.y;
            }
            if (DOT){
                float a0=sAs[lcol], a1=sAs[lcol+1], d0=sAd[lcol], d1=sAd[lcol+1];
                ds0 += v0.x*a0 + v0.y*a1;  dd0 += v0.x*d0 + v0.y*d1;
                ds1 += v1.x*a0 + v1.y*a1;  dd1 += v1.x*d0 + v1.y*d1;
                if (docs){
                    colp[nt*2]   += v0.x + v1.x;
                    colp[nt*2+1] += v0.y + v1.y;
                }
            }
            if (Cf){
                *(float2*)&Cf[(size_t)orow*ND + col]     = v0;
                *(float2*)&Cf[(size_t)(orow+8)*ND + col] = v1;
            }
            if (Ch){
                *(__half2*)&Ch[(size_t)orow*ND + col]     = __float22half2_rn(v0);
                *(__half2*)&Ch[(size_t)(orow+8)*ND + col] = __float22half2_rn(v1);
            }
        }
        if (DOT){
            ds0 += __shfl_down_sync(0xffffffffu, ds0, 2, 4); ds0 += __shfl_down_sync(0xffffffffu, ds0, 1, 4);
            dd0 += __shfl_down_sync(0xffffffffu, dd0, 2, 4); dd0 += __shfl_down_sync(0xffffffffu, dd0, 1, 4);
            ds1 += __shfl_down_sync(0xffffffffu, ds1, 2, 4); ds1 += __shfl_down_sync(0xffffffffu, ds1, 1, 4);
            dd1 += __shfl_down_sync(0xffffffffu, dd1, 2, 4); dd1 += __shfl_down_sync(0xffffffffu, dd1, 1, 4);
            if (qid==0){
                int rl = wm + mt*16 + gid;
                atomicAdd(&sdot[rl],     ds0); atomicAdd(&sdot[rl+8],     ds1);
                atomicAdd(&sdot[128+rl], dd0); atomicAdd(&sdot[128+rl+8], dd1);
            }
        }
    }
    if (docs){
        #pragma unroll
        for (int i=0;i<8;i++){
            colp[i] += __shfl_down_sync(0xffffffffu, colp[i], 16);
            colp[i] += __shfl_down_sync(0xffffffffu, colp[i], 8);
            colp[i] += __shfl_down_sync(0xffffffffu, colp[i], 4);
        }
        if (lane < 4){
            #pragma unroll
            for (int nt=0;nt<4;nt++){
                atomicAdd(&scol[wn + nt*8 + qid*2],     colp[nt*2]);
                atomicAdd(&scol[wn + nt*8 + qid*2 + 1], colp[nt*2+1]);
            }
        }
    }
    if (DOT){
        __syncthreads();
        if (tid<128){
            if (DOT==1){
                size_t idx = ((size_t)e*BSq + m0 + tid)*8 + (n0>>6);
                g_es[idx]  = sdot[tid];
                g_edh[idx] = __float2half(sdot[128+tid]);
            } else {
                atomicAdd(&g_gs[(size_t)e*BSq + m0 + tid], sdot[tid]);
                atomicAdd(&g_gd[(size_t)e*BSq + m0 + tid], sdot[128+tid]);
            }
        }
        if (docs && tid<64){
            int eb = e*Bq + (m0>>10);
            if (DOT==1) atomicAdd(&g_hsum [(size_t)eb*NHq + n0 + tid], scol[tid]);
            else        atomicAdd(&g_h2sum[(size_t)eb*Dq  + n0 + tid], scol[tid]);
        }
    }
    if (SIG){
        sred[tid] = lsum;
        __syncthreads();
        for (int st=128; st>0; st>>=1){ if (tid<st) sred[tid]+=sred[tid+st]; __syncthreads(); }
        if (tid==0) atomicAdd(&g_bwsum, sred[0]);
    }
}

// ---------------- attention layer 1 (single-pass softmax, fp16 weights, __expf) ----
__global__ void __launch_bounds__(192) k_att1(){
    __shared__ unsigned short lst[1024];
    __shared__ unsigned char  ok[1024];
    __shared__ __half wh[6*1024];
    __shared__ float sred[6][8];
    __shared__ float ssum[6];
    __shared__ float es6[6];
    __shared__ float4 sacc[2][96];
    int bs = blockIdx.x, ex = blockIdx.y, b = bs>>10;
    int tid = threadIdx.x, lane = tid&31, wid = tid>>5;
    int c1 = g_cnt[bs*4+0], c2 = g_cnt[bs*4+1], ct = g_cnt[bs*4+2];
    int lo, hi;
    if      (ex==0){ lo=0;  hi=ct; }
    else if (ex==1){ lo=0;  hi=c1; }
    else if (ex==2){ lo=c1; hi=c2; }
    else           { lo=c2; hi=ct; }
    int n = hi-lo;
    __half* h1row = g_h1h + ((size_t)ex*BSq + bs)*NHq;
    if (n==0){
        if (tid<96){
            float4 hv = *(const float4*)&g_hsum[(size_t)((ex<<2)|b)*NHq + tid*4];
            *(__half2*)&h1row[tid*4]   = __float22half2_rn(make_float2(elu1(hv.x*(1.f/Sq)), elu1(hv.y*(1.f/Sq))));
            *(__half2*)&h1row[tid*4+2] = __float22half2_rn(make_float2(elu1(hv.z*(1.f/Sq)), elu1(hv.w*(1.f/Sq))));
        }
        return;
    }
    for (int j=tid;j<n;j+=192) lst[j] = g_lst[(size_t)bs*Sq + lo + j];
    if (tid<6) es6[tid] = g_es[((size_t)ex*BSq + bs)*8 + tid];
    __syncthreads();
    const __half* edb = g_edh + ((size_t)ex*BSq + ((size_t)b<<10))*8;
    const unsigned char* rm = (ex>0)? g_rmask + (size_t)(ex-1)*BSq + (b<<10) : nullptr;
    // single pass: w = exp(logit - 4) (constant cancels in normalization; bounds fp16)
    float sm[6] = {0.f,0.f,0.f,0.f,0.f,0.f};
    for (int j=tid;j<n;j+=192){
        int nb = lst[j];
        uint4 raw = *(const uint4*)&edb[nb*8];
        ok[j] = rm ? rm[nb] : 1;
        float2 q0 = __half22float2(*(__half2*)&raw.x);
        float2 q1 = __half22float2(*(__half2*)&raw.y);
        float2 q2 = __half22float2(*(__half2*)&raw.z);
        float ev[6] = {q0.x,q0.y,q1.x,q1.y,q2.x,q2.y};
        #pragma unroll
        for (int h=0;h<6;h++){
            float ww = __expf(leaky02(es6[h] + ev[h]) - 4.f);
            wh[h*1024+j] = __float2half(ww);
            sm[h] += ww;
        }
    }
    #pragma unroll
    for (int h=0;h<6;h++){
        #pragma unroll
        for (int o=16;o>0;o>>=1) sm[h] += __shfl_xor_sync(0xffffffffu, sm[h], o);
    }
    if (lane==0){
        #pragma unroll
        for (int h=0;h<6;h++) sred[h][wid] = sm[h];
    }
    __syncthreads();
    if (tid<6){
        float s = sred[tid][0];
        #pragma unroll
        for (int wdx=1; wdx<6; wdx++) s += sred[tid][wdx];
        ssum[tid] = s;
    }
    __syncthreads();
    {
        int col = tid % 96, grp = tid / 96;
        int h = col >> 4;
        const __half* hb = g_hh + ((size_t)ex*BSq + ((size_t)b<<10))*NHq;
        float ax=0.f, ay=0.f, az=0.f, aw=0.f;
        if (ex==0){
            int j = grp;
            for (; j+2 < n; j += 4){
                float w0 = __half2float(wh[h*1024+j]);
                float w1 = __half2float(wh[h*1024+j+2]);
                uint2 r0 = *(const uint2*)&hb[(size_t)lst[j]*NHq   + col*4];
                uint2 r1 = *(const uint2*)&hb[(size_t)lst[j+2]*NHq + col*4];
                float2 p00 = __half22float2(*(__half2*)&r0.x);
                float2 p01 = __half22float2(*(__half2*)&r0.y);
                float2 p10 = __half22float2(*(__half2*)&r1.x);
                float2 p11 = __half22float2(*(__half2*)&r1.y);
                ax += w0*p00.x + w1*p10.x; ay += w0*p00.y + w1*p10.y;
                az += w0*p01.x + w1*p11.x; aw += w0*p01.y + w1*p11.y;
            }
            for (; j < n; j += 2){
                float w0 = __half2float(wh[h*1024+j]);
                uint2 r0 = *(const uint2*)&hb[(size_t)lst[j]*NHq + col*4];
                float2 p00 = __half22float2(*(__half2*)&r0.x);
                float2 p01 = __half22float2(*(__half2*)&r0.y);
                ax += w0*p00.x; ay += w0*p00.y; az += w0*p01.x; aw += w0*p01.y;
            }
        } else {
            for (int j=grp; j<n; j+=2){
                if (!ok[j]) continue;
                float w0 = __half2float(wh[h*1024+j]);
                uint2 r0 = *(const uint2*)&hb[(size_t)lst[j]*NHq + col*4];
                float2 p00 = __half22float2(*(__half2*)&r0.x);
                float2 p01 = __half22float2(*(__half2*)&r0.y);
                ax += w0*p00.x; ay += w0*p00.y; az += w0*p01.x; aw += w0*p01.y;
            }
        }
        sacc[grp][col] = make_float4(ax,ay,az,aw);
    }
    __syncthreads();
    if (tid<96){
        int h = tid >> 4;
        float inv = 1.f/ssum[h];
        float4 a0 = sacc[0][tid], a1 = sacc[1][tid];
        *(__half2*)&h1row[tid*4]   = __float22half2_rn(make_float2(elu1((a0.x+a1.x)*inv), elu1((a0.y+a1.y)*inv)));
        *(__half2*)&h1row[tid*4+2] = __float22half2_rn(make_float2(elu1((a0.z+a1.z)*inv), elu1((a0.w+a1.w)*inv)));
    }
}

// ---------------- attention layer 2 (single-pass softmax, __expf) ----------------
__global__ void __launch_bounds__(256) k_att2(){
    __shared__ unsigned short lst[1024];
    __shared__ float w[1024];
    __shared__ float red[256];
    __shared__ float4 sacc[4][64];
    int bs = blockIdx.x, ex = blockIdx.y, b = bs>>10;
    int tid = threadIdx.x;
    if (ex>0 && g_rmask[(size_t)(ex-1)*BSq + bs]==0) return;
    float* outb = (ex==0)? g_main : g_depE + (size_t)(ex-1)*BSDq;
    int c1 = g_cnt[bs*4+0], c2 = g_cnt[bs*4+1], ct = g_cnt[bs*4+2];
    int lo, hi;
    if      (ex==0){ lo=0;  hi=ct; }
    else if (ex==1){ lo=0;  hi=c1; }
    else if (ex==2){ lo=c1; hi=c2; }
    else           { lo=c2; hi=ct; }
    int n = hi-lo;
    if (n==0){
        if (tid<64){
            float4 hv = *(const float4*)&g_h2sum[(size_t)((ex<<2)|b)*Dq + tid*4];
            *(float4*)&outb[(size_t)bs*Dq + tid*4] =
                make_float4(hv.x*(1.f/Sq), hv.y*(1.f/Sq), hv.z*(1.f/Sq), hv.w*(1.f/Sq));
        }
        return;
    }
    for (int j=tid;j<n;j+=256) lst[j] = g_lst[(size_t)bs*Sq + lo + j];
    __syncthreads();
    float gsv = g_gs[(size_t)ex*BSq + bs];
    const float* gdb = g_gd + (size_t)ex*BSq + (b<<10);
    float sloc = 0.f;
    for (int j=tid;j<n;j+=256){
        float ww = __expf(leaky02(gsv + gdb[lst[j]]));
        w[j] = ww;
        sloc += ww;
    }
    red[tid]=sloc; __syncthreads();
    for (int st=128;st>0;st>>=1){ if (tid<st) red[tid]+=red[tid+st]; __syncthreads(); }
    float inv = 1.f/red[0];
    int grp = tid>>6, q = tid&63;
    const __half* h2b = g_h2h + ((size_t)ex*BSq + ((size_t)b<<10))*Dq;
    float ax=0.f, ay=0.f, az=0.f, aw=0.f;
    int j = grp;
    for (; j+4 < n; j += 8){
        float w0 = w[j], w1 = w[j+4];
        uint2 r0 = *(const uint2*)&h2b[(size_t)lst[j]*Dq   + q*4];
        uint2 r1 = *(const uint2*)&h2b[(size_t)lst[j+4]*Dq + q*4];
        float2 p00 = __half22float2(*(__half2*)&r0.x);
        float2 p01 = __half22float2(*(__half2*)&r0.y);
        float2 p10 = __half22float2(*(__half2*)&r1.x);
        float2 p11 = __half22float2(*(__half2*)&r1.y);
        ax += w0*p00.x + w1*p10.x; ay += w0*p00.y + w1*p10.y;
        az += w0*p01.x + w1*p11.x; aw += w0*p01.y + w1*p11.y;
    }
    for (; j < n; j += 4){
        float w0 = w[j];
        uint2 r0 = *(const uint2*)&h2b[(size_t)lst[j]*Dq + q*4];
        float2 p00 = __half22float2(*(__half2*)&r0.x);
        float2 p01 = __half22float2(*(__half2*)&r0.y);
        ax += w0*p00.x; ay += w0*p00.y; az += w0*p01.x; aw += w0*p01.y;
    }
    sacc[grp][q] = make_float4(ax,ay,az,aw);
    __syncthreads();
    if (tid<64){
        float4 a0=sacc[0][tid], a1=sacc[1][tid], a2=sacc[2][tid], a3=sacc[3][tid];
        *(float4*)&outb[(size_t)bs*Dq + tid*4] =
            make_float4((a0.x+a1.x+a2.x+a3.x)*inv, (a0.y+a1.y+a2.y+a3.y)*inv,
                        (a0.z+a1.z+a2.z+a3.z)*inv, (a0.w+a1.w+a2.w+a3.w)*inv);
    }
}

// ---------------- final blend ----------------
__global__ void k_final(float* __restrict__ out){
    __shared__ unsigned char msk[3];
    int bs = blockIdx.x, d = threadIdx.x;
    if (d<3) msk[d] = g_rmask[d*BSq+bs];
    __syncthreads();
    size_t i = (size_t)bs*Dq + d;
    float dep = 0.f;
    if (msk[0]) dep += g_depE[i];
    if (msk[1]) dep += g_depE[BSDq + i];
    if (msk[2]) dep += g_depE[2*(size_t)BSDq + i];
    float bw = g_bw[i];
    out[i] = bw*g_main[i] + (1.f-bw)*dep;
    if (bs==0 && d==0){
        float mc = g_bwsum * (1.f/(float)BSDq);
        out[BSDq]   = fabsf(mc - 0.6f) * 0.01f;
        out[BSDq+1] = mc;
    }
}

// ---------------- host launcher ----------------
extern "C" void kernel_launch(void* const* d_in, const int* in_sizes, int n_in,
                              void* d_out, int out_size){
    const float* feature  = (const float*)d_in[0];
    const float* adj      = (const float*)d_in[1];
    const float* main_W1  = (const float*)d_in[2];
    const float* main_a1s = (const float*)d_in[3];
    const float* main_a1d = (const float*)d_in[4];
    const float* main_W2  = (const float*)d_in[5];
    const float* main_a2s = (const float*)d_in[6];
    const float* main_a2d = (const float*)d_in[7];
    const float* dep_W1   = (const float*)d_in[8];
    const float* dep_a1s  = (const float*)d_in[9];
    const float* dep_a1d  = (const float*)d_in[10];
    const float* dep_W2   = (const float*)d_in[11];
    const float* dep_a2s  = (const float*)d_in[12];
    const float* dep_a2d  = (const float*)d_in[13];
    const float* router_W = (const float*)d_in[14];
    const float* blend_W  = (const float*)d_in[15];
    const float* blend_b  = (const float*)d_in[16];
    const int*   doc_num  = (const int*)d_in[17];
    const int*   sect_num = (const int*)d_in[18];
    float* out = (float*)d_out;

    __half* feat_h;  cudaGetSymbolAddress((void**)&feat_h,  g_feat_h);
    __half* W1t_h;   cudaGetSymbolAddress((void**)&W1t_h,   g_W1t_h);
    __half* W2t_h;   cudaGetSymbolAddress((void**)&W2t_h,   g_W2t_h);
    __half* bWt_h;   cudaGetSymbolAddress((void**)&bWt_h,   g_bWt_h);
    __half* h1h_p;   cudaGetSymbolAddress((void**)&h1h_p,   g_h1h);
    float*  bw_p;    cudaGetSymbolAddress((void**)&bw_p,    g_bw);
    __half* hh_p;    cudaGetSymbolAddress((void**)&hh_p,    g_hh);
    __half* h2h_p;   cudaGetSymbolAddress((void**)&h2h_p,   g_h2h);

    k_prep<<<dim3(BSq*Dq/256, 7), 256>>>(feature, main_W1, dep_W1, main_W2, dep_W2,
                                         blend_W, router_W, adj, doc_num, sect_num);

    k_mmh<Dq, Dq, false, true, 0><<<dim3(4,32,1), 256>>>(feat_h, 0, bWt_h, bw_p, (__half*)0, blend_b,
                                                         (const float*)0,(const float*)0,(const float*)0,(const float*)0);

    k_mmh<Dq, NHq, true, false, 1><<<dim3(6,32,NEXP), 256>>>(feat_h, 0, W1t_h, (float*)0, hh_p, (const float*)0,
                                                             main_a1s, dep_a1s, main_a1d, dep_a1d);
    k_att1<<<dim3(BSq, NEXP), 192>>>();

    k_mmh<NHq, Dq, false, false, 2><<<dim3(4,32,NEXP), 256>>>(h1h_p, (size_t)BSq*NHq, W2t_h, (float*)0, h2h_p, (const float*)0,
                                                              main_a2s, dep_a2s, main_a2d, dep_a2d);
    k_att2<<<dim3(BSq, NEXP), 256>>>();

    k_final<<<BSq, Dq>>>(out);
}